// round 14
// baseline (speedup 1.0000x reference)
#include <cuda_runtime.h>
#include <cuda_fp16.h>
#include <cstdint>

// Problem constants
#define BB 4
#define CC 256
#define FF 16
#define PP 1024                 // H*W
#define NN 64                   // B*F
#define CP (CC*PP)              // 262144
#define CFP (CC*FF*PP)          // 4194304

#define LO_SCALE   2048.0f
#define LO_INV     (1.0f/2048.0f)

// Scratch (allocation-guard-safe static device arrays). __align__(16): uint4/cp.async.
__device__ __align__(16) float g_q[(size_t)NN*CP];
__device__ __align__(16) float g_k[(size_t)NN*CP];
__device__ __align__(16) float g_v[(size_t)NN*CP];
__device__ __align__(16) __half g_whi[3*CC*CC];
__device__ __align__(16) __half g_wlo[3*CC*CC];
__device__ __align__(16) __half g_xthi[(size_t)NN*PP*CC];   // x hi, transposed [n][p][c]
__device__ __align__(16) __half g_xtlo[(size_t)NN*PP*CC];   // x lo (x2048), transposed

__device__ __forceinline__ uint32_t smem_u32(const void* p) {
    uint32_t a;
    asm("{ .reg .u64 t; cvta.to.shared.u64 t, %1; cvt.u32.u64 %0, t; }" : "=r"(a) : "l"(p));
    return a;
}

__device__ __forceinline__ void split_hi_lo(float v, __half& h, __half& l) {
    uint32_t bi = __float_as_uint(v);
    float hf = __uint_as_float(bi & 0xFFFFE000u);   // top 10 explicit mantissa bits
    h = __float2half_rn(hf);                        // exact in normal range
    l = __float2half_rn((v - hf) * LO_SCALE);
}

#define MMA16816(C, A, B)                                                     \
    asm volatile("mma.sync.aligned.m16n8k16.row.col.f32.f16.f16.f32 "         \
                 "{%0,%1,%2,%3}, {%4,%5,%6,%7}, {%8,%9}, {%0,%1,%2,%3};"      \
                 : "+f"((C)[0]), "+f"((C)[1]), "+f"((C)[2]), "+f"((C)[3])     \
                 : "r"((A)[0]), "r"((A)[1]), "r"((A)[2]), "r"((A)[3]),        \
                   "r"((B)[0]), "r"((B)[1]))

#define LDMX4(R, ADDR)                                                        \
    asm volatile("ldmatrix.sync.aligned.m8n8.x4.shared.b16 {%0,%1,%2,%3}, [%4];" \
                 : "=r"((R)[0]), "=r"((R)[1]), "=r"((R)[2]), "=r"((R)[3])     \
                 : "r"(ADDR))

#define LDMX2(R, ADDR)                                                        \
    asm volatile("ldmatrix.sync.aligned.m8n8.x2.shared.b16 {%0,%1}, [%2];"    \
                 : "=r"((R)[0]), "=r"((R)[1]) : "r"(ADDR))

#define CP16(SADDR, GPTR)                                                     \
    asm volatile("cp.async.ca.shared.global [%0], [%1], 16;"                  \
                 :: "r"(SADDR), "l"(GPTR))

// ---------------------------------------------------------------------------
// Kernel 0a: split weights fp32 -> fp16 hi + scaled lo residual
// ---------------------------------------------------------------------------
__global__ __launch_bounds__(512) void r14_wsplit(
    const float* __restrict__ wq, const float* __restrict__ wk, const float* __restrict__ wv)
{
    int idx = blockIdx.x * 512 + threadIdx.x;
    const float* src = (idx < 65536) ? wq : (idx < 131072 ? wk : wv);
    float v = src[idx & 65535];
    __half h, l;
    split_hi_lo(v, h, l);
    g_whi[idx] = h;
    g_wlo[idx] = l;
}

// ---------------------------------------------------------------------------
// Kernel 0b: split + transpose x: [n][c][p] fp32 -> [n][p][c] fp16 hi/lo.
// Tile stride 68 floats (16B-aligned rows).
// ---------------------------------------------------------------------------
__global__ __launch_bounds__(256) void r14_xsplit(const float* __restrict__ x)
{
    __shared__ __align__(16) float tile[64][68];
    const int pt = blockIdx.x * 64;
    const int ct = blockIdx.y * 64;
    const int n  = blockIdx.z;
    const int t  = threadIdx.x;

    const float* __restrict__ xn = x + (size_t)n * CP;
    {
        int c   = t >> 2;
        int pc0 = (t & 3) * 16;
        const float* src = xn + (size_t)(ct + c) * PP + pt + pc0;
        #pragma unroll
        for (int u = 0; u < 4; u++)
            *(float4*)&tile[c][pc0 + u * 4] = *(const float4*)(src + u * 4);
    }
    __syncthreads();
    {
        int p   = t >> 2;
        int cc0 = (t & 3) * 16;
        __align__(16) __half hbuf[16], lbuf[16];
        #pragma unroll
        for (int u = 0; u < 16; u++) {
            __half h, l;
            split_hi_lo(tile[cc0 + u][p], h, l);
            hbuf[u] = h; lbuf[u] = l;
        }
        size_t dst = (size_t)n * PP * CC + (size_t)(pt + p) * CC + ct + cc0;
        *(uint4*)(g_xthi + dst)     = *(uint4*)hbuf;
        *(uint4*)(g_xthi + dst + 8) = *(uint4*)(hbuf + 8);
        *(uint4*)(g_xtlo + dst)     = *(uint4*)lbuf;
        *(uint4*)(g_xtlo + dst + 8) = *(uint4*)(lbuf + 8);
    }
}

// ---------------------------------------------------------------------------
// Kernel 1: QKV projection GEMM, 128d x 64p tile, cp.async double-buffered,
// 2 CTAs/SM. 3-term split: W.X = Wh.Xh + (Wl.Xh + Wh.Xl)*2^-11.
// Grid: (16 p-tiles, m*2+dh, n) = (16, 6, 64).
// smem/stage: Ah 5120h | Al 5120h | Bh 2560h | Bl 2560h = 30720 B; x2 stages.
// ---------------------------------------------------------------------------
#define AH_T 5120             // halves: 128 rows * 40
#define BH_T 2560             // halves: 64 rows * 40
#define STAGE_H (2*AH_T + 2*BH_T)   // 15360 halves = 30720 B
#define PROJ_SMEM (2*STAGE_H*2)     // 61440 B

__global__ __launch_bounds__(256, 2) void r14_proj(
    const float* __restrict__ bq,
    const float* __restrict__ bk,
    const float* __restrict__ bv)
{
    extern __shared__ __align__(16) __half sh[];

    const int p0 = blockIdx.x * 64;         // 0..15 (p tile)
    const int m  = blockIdx.y >> 1;         // 0..2
    const int d0 = (blockIdx.y & 1) * 128;  // 0 or 128
    const int n  = blockIdx.z;              // 0..63
    const int t  = threadIdx.x;
    const int lane = t & 31;
    const int wid  = t >> 5;
    const int wm   = wid & 3;               // 0..3 (32 d rows each)
    const int wn   = wid >> 2;              // 0..1 (32 p rows each)

    const __half* __restrict__ whp = g_whi + (size_t)m * 65536;
    const __half* __restrict__ wlp = g_wlo + (size_t)m * 65536;
    const size_t nb = (size_t)n * PP * CC;
    const uint32_t sbase = smem_u32(sh);

    float chi[2][4][4], clo[2][4][4];
    #pragma unroll
    for (int mi = 0; mi < 2; mi++)
        #pragma unroll
        for (int ni = 0; ni < 4; ni++)
            #pragma unroll
            for (int r = 0; r < 4; r++) { chi[mi][ni][r] = 0.f; clo[mi][ni][r] = 0.f; }

    // cp.async task decomposition (per chunk):
    // A (hi,lo): 128 rows x 64 B = 512 16B-segments each -> thread does 2
    // B (hi,lo): 64 rows x 64 B = 256 segments each -> thread does 1
    #define ISSUE(kc, stage) do {                                               \
        uint32_t base = sbase + (uint32_t)(stage)*STAGE_H*2;                    \
        _Pragma("unroll")                                                       \
        for (int u = 0; u < 2; u++) {                                           \
            int sid = t + u*256;                                                \
            int row = sid >> 2, sg = sid & 3;                                   \
            uint32_t so = base + (uint32_t)(row*40 + sg*8)*2;                   \
            size_t go = (size_t)(d0 + row)*256 + (kc)*32 + sg*8;                \
            CP16(so, whp + go);                                                 \
            CP16(so + AH_T*2, wlp + go);                                        \
        }                                                                       \
        {                                                                       \
            int row = t >> 2, sg = t & 3;                                       \
            uint32_t so = base + (uint32_t)(2*AH_T + row*40 + sg*8)*2;          \
            size_t go = nb + (size_t)(p0 + row)*CC + (kc)*32 + sg*8;            \
            CP16(so, g_xthi + go);                                              \
            CP16(so + BH_T*2, g_xtlo + go);                                     \
        }                                                                       \
        asm volatile("cp.async.commit_group;" ::: "memory");                    \
    } while (0)

    ISSUE(0, 0);
    ISSUE(1, 1);

    #pragma unroll 1
    for (int kc = 0; kc < 8; kc++) {
        if (kc < 7) asm volatile("cp.async.wait_group 1;" ::: "memory");
        else        asm volatile("cp.async.wait_group 0;" ::: "memory");
        __syncthreads();

        const uint32_t st = sbase + (uint32_t)(kc & 1)*STAGE_H*2;
        const uint32_t ah_s = st;
        const uint32_t al_s = st + AH_T*2;
        const uint32_t bh_s = st + 2*AH_T*2;
        const uint32_t bl_s = st + (2*AH_T + BH_T)*2;

        #pragma unroll
        for (int ks = 0; ks < 2; ks++) {
            const uint32_t a_off = (uint32_t)((wm*32 + (lane & 15))*40 + ks*16 + (lane >> 4)*8) * 2;
            const uint32_t b_off = (uint32_t)((wn*32 + (lane & 7))*40 + ks*16 + ((lane >> 3) & 1)*8) * 2;

            uint32_t afh[2][4], afl[2][4], bfh[4][2], bfl[4][2];
            #pragma unroll
            for (int mi = 0; mi < 2; mi++) {
                LDMX4(afh[mi], ah_s + a_off + (uint32_t)(mi*16*40)*2);
                LDMX4(afl[mi], al_s + a_off + (uint32_t)(mi*16*40)*2);
            }
            #pragma unroll
            for (int ni = 0; ni < 4; ni++) {
                LDMX2(bfh[ni], bh_s + b_off + (uint32_t)(ni*8*40)*2);
                LDMX2(bfl[ni], bl_s + b_off + (uint32_t)(ni*8*40)*2);
            }
            #pragma unroll
            for (int mi = 0; mi < 2; mi++)
                #pragma unroll
                for (int ni = 0; ni < 4; ni++) {
                    MMA16816(chi[mi][ni], afh[mi], bfh[ni]);
                    MMA16816(clo[mi][ni], afl[mi], bfh[ni]);
                    MMA16816(clo[mi][ni], afh[mi], bfl[ni]);
                }
        }
        __syncthreads();
        if (kc < 6) ISSUE(kc + 2, kc & 1);
    }

    // ---- epilogue: combine hi + lo*2^-11, add bias, store fp32
    const float* __restrict__ bias = (m == 0) ? bq : (m == 1) ? bk : bv;
    float* __restrict__ ob = (m == 0) ? g_q : (m == 1) ? g_k : g_v;
    const int gid = lane >> 2, tid4 = lane & 3;
    const int col = p0 + wn*32 + tid4*2;

    #pragma unroll
    for (int mi = 0; mi < 2; mi++) {
        int d_r = d0 + wm*32 + mi*16 + gid;
        float b0 = bias[d_r];
        float b1 = bias[d_r + 8];
        float* o0 = ob + (size_t)n*CP + (size_t)d_r*PP + col;
        float* o1 = o0 + (size_t)8*PP;
        #pragma unroll
        for (int ni = 0; ni < 4; ni++) {
            float r0 = fmaf(clo[mi][ni][0], LO_INV, chi[mi][ni][0]) + b0;
            float r1 = fmaf(clo[mi][ni][1], LO_INV, chi[mi][ni][1]) + b0;
            float r2 = fmaf(clo[mi][ni][2], LO_INV, chi[mi][ni][2]) + b1;
            float r3 = fmaf(clo[mi][ni][3], LO_INV, chi[mi][ni][3]) + b1;
            *(float2*)(o0 + ni*8) = make_float2(r0, r1);
            *(float2*)(o1 + ni*8) = make_float2(r2, r3);
        }
    }
    #undef ISSUE
}

// ---------------------------------------------------------------------------
// Kernel 2: per-(b,c) temporal attention, 512 threads (acc[16][2], ~47% occ).
// ---------------------------------------------------------------------------
#define QS 264

__global__ __launch_bounds__(512, 2) void r14_attn(
    const float* __restrict__ x,
    const float* __restrict__ gamma,
    float* __restrict__ out)
{
    __shared__ float qs[16][QS];
    __shared__ float ks[16][QS];
    __shared__ float S[16][17];
    __shared__ float Pm[16][16];

    const int bc = blockIdx.x;
    const int b  = bc >> 8;
    const int c  = bc & 255;
    const int t  = threadIdx.x;

    const size_t qbase = (size_t)(b * 16) * CP + (size_t)c * PP;

    // logits: pair = t>>1 handles (i,j); half = t&1 handles 128 of each 256-chunk
    const int pair = t >> 1, half = t & 1;
    const int i = pair >> 4, j = pair & 15;
    float s0 = 0.f, s1 = 0.f, s2 = 0.f, s3 = 0.f;
    #pragma unroll 1
    for (int ch = 0; ch < 4; ch++) {
        __syncthreads();
        {
            int fr = t >> 5, q0 = t & 31;
            size_t base = qbase + (size_t)fr * CP + ch * 256;
            #pragma unroll
            for (int u = 0; u < 2; u++) {
                *(float4*)&qs[fr][(q0 + u * 32) * 4] = *(const float4*)&g_q[base + (q0 + u * 32) * 4];
                *(float4*)&ks[fr][(q0 + u * 32) * 4] = *(const float4*)&g_k[base + (q0 + u * 32) * 4];
            }
        }
        __syncthreads();
        const float* qp = &qs[i][half * 128];
        const float* kp = &ks[j][half * 128];
        #pragma unroll 8
        for (int p = 0; p < 128; p += 4) {
            float4 a = *(const float4*)&qp[p];
            float4 bb = *(const float4*)&kp[p];
            s0 += a.x * bb.x; s1 += a.y * bb.y; s2 += a.z * bb.z; s3 += a.w * bb.w;
        }
    }
    {
        float st = (s0 + s1) + (s2 + s3);
        st += __shfl_xor_sync(0xFFFFFFFFu, st, 1);
        if (half == 0) S[i][j] = st;
    }
    __syncthreads();

    // softmax rows (scale 1/sqrt(256))
    if (t < 16) {
        float mx = -1e30f;
        float e[16];
        #pragma unroll
        for (int jj = 0; jj < 16; jj++) {
            float v = S[t][jj] * 0.0625f;
            e[jj] = v;
            mx = fmaxf(mx, v);
        }
        float sum = 0.f;
        #pragma unroll
        for (int jj = 0; jj < 16; jj++) { e[jj] = __expf(e[jj] - mx); sum += e[jj]; }
        float inv = 1.f / sum;
        #pragma unroll
        for (int jj = 0; jj < 16; jj++) Pm[t][jj] = e[jj] * inv;
    }
    __syncthreads();

    // out[i][p] = sum_j Pm[i][j] * v[j][p]; thread owns p = t and t+512
    float acc[16][2];
    #pragma unroll
    for (int ii = 0; ii < 16; ii++) { acc[ii][0] = 0.f; acc[ii][1] = 0.f; }

    #pragma unroll 1
    for (int jj = 0; jj < 16; jj++) {
        const float* vp = &g_v[qbase + (size_t)jj * CP];
        float v0 = vp[t];
        float v1 = vp[t + 512];
        #pragma unroll
        for (int ii = 0; ii < 16; ii++) {
            float pij = Pm[ii][jj];
            acc[ii][0] += pij * v0;
            acc[ii][1] += pij * v1;
        }
    }

    const float g = gamma[0];
    const size_t xbase = (size_t)b * CFP + (size_t)c * (FF * PP);
    #pragma unroll
    for (int ii = 0; ii < 16; ii++) {
        size_t idx = xbase + (size_t)ii * PP + t;
        out[idx]       = g * acc[ii][0] + x[idx];
        out[idx + 512] = g * acc[ii][1] + x[idx + 512];
    }
}

// ---------------------------------------------------------------------------
extern "C" void kernel_launch(void* const* d_in, const int* in_sizes, int n_in,
                              void* d_out, int out_size)
{
    const float* x     = (const float*)d_in[0];
    const float* wq    = (const float*)d_in[1];
    const float* bq    = (const float*)d_in[2];
    const float* wk    = (const float*)d_in[3];
    const float* bk    = (const float*)d_in[4];
    const float* wv    = (const float*)d_in[5];
    const float* bv    = (const float*)d_in[6];
    const float* gamma = (const float*)d_in[7];
    float* out = (float*)d_out;

    cudaFuncSetAttribute(r14_proj,
                         cudaFuncAttributeMaxDynamicSharedMemorySize, PROJ_SMEM);

    r14_wsplit<<<384, 512>>>(wq, wk, wv);
    r14_xsplit<<<dim3(16, 4, 64), 256>>>(x);
    r14_proj<<<dim3(16, 6, 64), 256, PROJ_SMEM>>>(bq, bk, bv);
    r14_attn<<<BB*CC, 512>>>(x, gamma, out);
}

// round 15
// speedup vs baseline: 1.0555x; 1.0555x over previous
#include <cuda_runtime.h>
#include <cuda_fp16.h>
#include <cstdint>

// Problem constants
#define BB 4
#define CC 256
#define FF 16
#define PP 1024                 // H*W
#define NN 64                   // B*F
#define CP (CC*PP)              // 262144
#define CFP (CC*FF*PP)          // 4194304

#define LO_SCALE   2048.0f
#define LO_INV     (1.0f/2048.0f)

// Scratch (allocation-guard-safe static device arrays). __align__(16): uint4/cp.async.
__device__ __align__(16) float g_q[(size_t)NN*CP];
__device__ __align__(16) float g_k[(size_t)NN*CP];
__device__ __align__(16) float g_v[(size_t)NN*CP];
__device__ __align__(16) __half g_whi[3*CC*CC];
__device__ __align__(16) __half g_wlo[3*CC*CC];
__device__ __align__(16) __half g_xthi[(size_t)NN*PP*CC];   // x hi, transposed [n][p][c]
__device__ __align__(16) __half g_xtlo[(size_t)NN*PP*CC];   // x lo (x2048), transposed

__device__ __forceinline__ uint32_t smem_u32(const void* p) {
    uint32_t a;
    asm("{ .reg .u64 t; cvta.to.shared.u64 t, %1; cvt.u32.u64 %0, t; }" : "=r"(a) : "l"(p));
    return a;
}

__device__ __forceinline__ void split_hi_lo(float v, __half& h, __half& l) {
    uint32_t bi = __float_as_uint(v);
    float hf = __uint_as_float(bi & 0xFFFFE000u);   // top 10 explicit mantissa bits
    h = __float2half_rn(hf);                        // exact in normal range
    l = __float2half_rn((v - hf) * LO_SCALE);
}

#define MMA16816(C, A, B)                                                     \
    asm volatile("mma.sync.aligned.m16n8k16.row.col.f32.f16.f16.f32 "         \
                 "{%0,%1,%2,%3}, {%4,%5,%6,%7}, {%8,%9}, {%0,%1,%2,%3};"      \
                 : "+f"((C)[0]), "+f"((C)[1]), "+f"((C)[2]), "+f"((C)[3])     \
                 : "r"((A)[0]), "r"((A)[1]), "r"((A)[2]), "r"((A)[3]),        \
                   "r"((B)[0]), "r"((B)[1]))

#define LDMX4(R, ADDR)                                                        \
    asm volatile("ldmatrix.sync.aligned.m8n8.x4.shared.b16 {%0,%1,%2,%3}, [%4];" \
                 : "=r"((R)[0]), "=r"((R)[1]), "=r"((R)[2]), "=r"((R)[3])     \
                 : "r"(ADDR))

#define LDMX2(R, ADDR)                                                        \
    asm volatile("ldmatrix.sync.aligned.m8n8.x2.shared.b16 {%0,%1}, [%2];"    \
                 : "=r"((R)[0]), "=r"((R)[1]) : "r"(ADDR))

#define CP16(SADDR, GPTR)                                                     \
    asm volatile("cp.async.ca.shared.global [%0], [%1], 16;"                  \
                 :: "r"(SADDR), "l"(GPTR))

// ---------------------------------------------------------------------------
// Kernel 0a: split weights fp32 -> fp16 hi + scaled lo residual
// ---------------------------------------------------------------------------
__global__ __launch_bounds__(512) void r15_wsplit(
    const float* __restrict__ wq, const float* __restrict__ wk, const float* __restrict__ wv)
{
    int idx = blockIdx.x * 512 + threadIdx.x;
    const float* src = (idx < 65536) ? wq : (idx < 131072 ? wk : wv);
    float v = src[idx & 65535];
    __half h, l;
    split_hi_lo(v, h, l);
    g_whi[idx] = h;
    g_wlo[idx] = l;
}

// ---------------------------------------------------------------------------
// Kernel 0b: split + transpose x: [n][c][p] fp32 -> [n][p][c] fp16 hi/lo.
// ---------------------------------------------------------------------------
__global__ __launch_bounds__(256) void r15_xsplit(const float* __restrict__ x)
{
    __shared__ __align__(16) float tile[64][68];
    const int pt = blockIdx.x * 64;
    const int ct = blockIdx.y * 64;
    const int n  = blockIdx.z;
    const int t  = threadIdx.x;

    const float* __restrict__ xn = x + (size_t)n * CP;
    {
        int c   = t >> 2;
        int pc0 = (t & 3) * 16;
        const float* src = xn + (size_t)(ct + c) * PP + pt + pc0;
        #pragma unroll
        for (int u = 0; u < 4; u++)
            *(float4*)&tile[c][pc0 + u * 4] = *(const float4*)(src + u * 4);
    }
    __syncthreads();
    {
        int p   = t >> 2;
        int cc0 = (t & 3) * 16;
        __align__(16) __half hbuf[16], lbuf[16];
        #pragma unroll
        for (int u = 0; u < 16; u++) {
            __half h, l;
            split_hi_lo(tile[cc0 + u][p], h, l);
            hbuf[u] = h; lbuf[u] = l;
        }
        size_t dst = (size_t)n * PP * CC + (size_t)(pt + p) * CC + ct + cc0;
        *(uint4*)(g_xthi + dst)     = *(uint4*)hbuf;
        *(uint4*)(g_xthi + dst + 8) = *(uint4*)(hbuf + 8);
        *(uint4*)(g_xtlo + dst)     = *(uint4*)lbuf;
        *(uint4*)(g_xtlo + dst + 8) = *(uint4*)(lbuf + 8);
    }
}

// ---------------------------------------------------------------------------
// Kernel 1: QKV projection GEMM (R13 structure, MMA-pipe-capped ~260us).
// 3-term split: W.X = Wh.Xh + (Wl.Xh + Wh.Xl)*2^-11.
// Grid: (8, 6, 64). CTA: C[128d x 128p], K=256 in 8 chunks, double-buffered.
// ---------------------------------------------------------------------------
#define TILE_H 5120   // halves per tile (128*40)
#define PROJ_SMEM 81920

__global__ __launch_bounds__(256, 1) void r15_proj(
    const float* __restrict__ bq,
    const float* __restrict__ bk,
    const float* __restrict__ bv)
{
    extern __shared__ __align__(16) __half sh[];
    __half* As = sh;
    __half* Bs = sh + 4 * TILE_H;

    const int p0 = blockIdx.x * 128;
    const int m  = blockIdx.y >> 1;
    const int d0 = (blockIdx.y & 1) * 128;
    const int n  = blockIdx.z;
    const int t  = threadIdx.x;
    const int lane = t & 31;
    const int wid  = t >> 5;
    const int wm   = wid & 1;
    const int wn   = wid >> 1;

    const __half* __restrict__ whp = g_whi + (size_t)m * 65536;
    const __half* __restrict__ wlp = g_wlo + (size_t)m * 65536;

    float chi[4][4][4], clo[4][4][4];
    #pragma unroll
    for (int mi = 0; mi < 4; mi++)
        #pragma unroll
        for (int ni = 0; ni < 4; ni++)
            #pragma unroll
            for (int r = 0; r < 4; r++) { chi[mi][ni][r] = 0.f; clo[mi][ni][r] = 0.f; }

    const int arow = t >> 1;
    const int acol = (t & 1) * 16;
    const int brow = t >> 1;
    const int bseg = (t & 1) * 16;

    const __half* __restrict__ bhbase =
        g_xthi + (size_t)n * PP * CC + (size_t)(p0 + brow) * CC + bseg;
    const __half* __restrict__ blbase =
        g_xtlo + (size_t)n * PP * CC + (size_t)(p0 + brow) * CC + bseg;

    uint4 rah0, rah1, ral0, ral1;
    uint4 rbh0, rbh1, rbl0, rbl1;

    #define TA_LDG(kc)                                                          \
        do {                                                                    \
            size_t wo = (size_t)(d0 + arow)*256 + (kc)*32 + acol;               \
            rah0 = *(const uint4*)(whp + wo);                                   \
            rah1 = *(const uint4*)(whp + wo + 8);                               \
            ral0 = *(const uint4*)(wlp + wo);                                   \
            ral1 = *(const uint4*)(wlp + wo + 8);                               \
            rbh0 = *(const uint4*)(bhbase + (kc)*32);                           \
            rbh1 = *(const uint4*)(bhbase + (kc)*32 + 8);                       \
            rbl0 = *(const uint4*)(blbase + (kc)*32);                           \
            rbl1 = *(const uint4*)(blbase + (kc)*32 + 8);                       \
        } while (0)

    #define TA_STS(buf)                                                         \
        do {                                                                    \
            __half* ah = As + (buf)*2*TILE_H;                                   \
            __half* al = ah + TILE_H;                                           \
            *(uint4*)&ah[arow*40 + acol]     = rah0;                            \
            *(uint4*)&ah[arow*40 + acol + 8] = rah1;                            \
            *(uint4*)&al[arow*40 + acol]     = ral0;                            \
            *(uint4*)&al[arow*40 + acol + 8] = ral1;                            \
            __half* bh = Bs + (buf)*2*TILE_H;                                   \
            __half* bl = bh + TILE_H;                                           \
            *(uint4*)&bh[brow*40 + bseg]     = rbh0;                            \
            *(uint4*)&bh[brow*40 + bseg + 8] = rbh1;                            \
            *(uint4*)&bl[brow*40 + bseg]     = rbl0;                            \
            *(uint4*)&bl[brow*40 + bseg + 8] = rbl1;                            \
        } while (0)

    TA_LDG(0);
    TA_STS(0);
    __syncthreads();

    #pragma unroll 1
    for (int kc = 0; kc < 8; kc++) {
        if (kc < 7) TA_LDG(kc + 1);

        const uint32_t ah_s = smem_u32(As + (kc & 1)*2*TILE_H);
        const uint32_t al_s = ah_s + TILE_H*2;
        const uint32_t bh_s = smem_u32(Bs + (kc & 1)*2*TILE_H);
        const uint32_t bl_s = bh_s + TILE_H*2;

        #pragma unroll
        for (int ks = 0; ks < 2; ks++) {
            const uint32_t a_off = (uint32_t)((wm*64 + (lane & 15))*40 + ks*16 + (lane >> 4)*8) * 2;
            const uint32_t b_off = (uint32_t)((wn*32 + (lane & 7))*40 + ks*16 + ((lane >> 3) & 1)*8) * 2;

            uint32_t afh[4][4], afl[4][4], bfh[4][2], bfl[4][2];
            #pragma unroll
            for (int mi = 0; mi < 4; mi++) {
                LDMX4(afh[mi], ah_s + a_off + (uint32_t)(mi*16*40)*2);
                LDMX4(afl[mi], al_s + a_off + (uint32_t)(mi*16*40)*2);
            }
            #pragma unroll
            for (int ni = 0; ni < 4; ni++) {
                LDMX2(bfh[ni], bh_s + b_off + (uint32_t)(ni*8*40)*2);
                LDMX2(bfl[ni], bl_s + b_off + (uint32_t)(ni*8*40)*2);
            }
            #pragma unroll
            for (int mi = 0; mi < 4; mi++)
                #pragma unroll
                for (int ni = 0; ni < 4; ni++) {
                    MMA16816(chi[mi][ni], afh[mi], bfh[ni]);
                    MMA16816(clo[mi][ni], afl[mi], bfh[ni]);
                    MMA16816(clo[mi][ni], afh[mi], bfl[ni]);
                }
        }

        if (kc < 7) TA_STS((kc + 1) & 1);
        __syncthreads();
    }

    const float* __restrict__ bias = (m == 0) ? bq : (m == 1) ? bk : bv;
    float* __restrict__ ob = (m == 0) ? g_q : (m == 1) ? g_k : g_v;
    const int gid = lane >> 2, tid4 = lane & 3;
    const int col = p0 + wn*32 + tid4*2;

    #pragma unroll
    for (int mi = 0; mi < 4; mi++) {
        int d_r = d0 + wm*64 + mi*16 + gid;
        float b0 = bias[d_r];
        float b1 = bias[d_r + 8];
        float* o0 = ob + (size_t)n*CP + (size_t)d_r*PP + col;
        float* o1 = o0 + (size_t)8*PP;
        #pragma unroll
        for (int ni = 0; ni < 4; ni++) {
            float r0 = fmaf(clo[mi][ni][0], LO_INV, chi[mi][ni][0]) + b0;
            float r1 = fmaf(clo[mi][ni][1], LO_INV, chi[mi][ni][1]) + b0;
            float r2 = fmaf(clo[mi][ni][2], LO_INV, chi[mi][ni][2]) + b1;
            float r3 = fmaf(clo[mi][ni][3], LO_INV, chi[mi][ni][3]) + b1;
            *(float2*)(o0 + ni*8) = make_float2(r0, r1);
            *(float2*)(o1 + ni*8) = make_float2(r2, r3);
        }
    }
    #undef TA_LDG
    #undef TA_STS
}

// ---------------------------------------------------------------------------
// Kernel 2: per-(b,c) temporal attention.
// cp.async 2-stage pipelined q/k chunk staging (double-buffered dynamic smem,
// 2 CTAs/SM); v-loop register double-buffered. 256 threads.
// ---------------------------------------------------------------------------
#define QSC 264                       // floats per chunk row (256 + 8 pad)
#define QBUF (16*QSC)                 // floats per buffer (one tensor, one stage)
#define ATTN_SMEM (4*QBUF*4)          // qs[2] + ks[2] = 67584 B

__global__ __launch_bounds__(256, 2) void r15_attn(
    const float* __restrict__ x,
    const float* __restrict__ gamma,
    float* __restrict__ out)
{
    extern __shared__ __align__(16) float smf[];
    // layout: qs0 | qs1 | ks0 | ks1, each QBUF floats
    __shared__ float S[16][17];
    __shared__ float Pm[16][16];

    const int bc = blockIdx.x;
    const int b  = bc >> 8;
    const int c  = bc & 255;
    const int t  = threadIdx.x;

    const size_t qbase = (size_t)(b * 16) * CP + (size_t)c * PP;
    const uint32_t sbase = smem_u32(smf);

    // issue cp.async for chunk ch into buffer bf: q,k each 16 rows x 1KB
    // = 1024 16B-segments each; thread does 4 q-segs + 4 k-segs.
    #define AT_ISSUE(ch, bf) do {                                               \
        _Pragma("unroll")                                                       \
        for (int u = 0; u < 4; u++) {                                           \
            int s = t + u * 256;                                                \
            int row = s >> 6, o16 = s & 63;                                     \
            uint32_t so = sbase + ((uint32_t)(bf)*QBUF + row*QSC + o16*4)*4;    \
            size_t go = qbase + (size_t)row*CP + (ch)*256 + o16*4;              \
            CP16(so, g_q + go);                                                 \
            CP16(so + 2*QBUF*4, g_k + go);                                      \
        }                                                                       \
        asm volatile("cp.async.commit_group;" ::: "memory");                    \
    } while (0)

    AT_ISSUE(0, 0);
    AT_ISSUE(1, 1);

    const int i = t >> 4, j = t & 15;
    float s0 = 0.f, s1 = 0.f, s2 = 0.f, s3 = 0.f;

    #pragma unroll 1
    for (int ch = 0; ch < 4; ch++) {
        if (ch < 3) asm volatile("cp.async.wait_group 1;" ::: "memory");
        else        asm volatile("cp.async.wait_group 0;" ::: "memory");
        __syncthreads();

        const float* qp = smf + (ch & 1)*QBUF + i*QSC;
        const float* kp = smf + (2 + (ch & 1))*QBUF + j*QSC;
        #pragma unroll 8
        for (int p = 0; p < 256; p += 4) {
            float4 a = *(const float4*)&qp[p];
            float4 bb = *(const float4*)&kp[p];
            s0 += a.x * bb.x; s1 += a.y * bb.y; s2 += a.z * bb.z; s3 += a.w * bb.w;
        }
        __syncthreads();
        if (ch < 2) AT_ISSUE(ch + 2, ch & 1);
    }
    S[i][j] = (s0 + s1) + (s2 + s3);
    __syncthreads();

    // softmax rows (scale 1/sqrt(256))
    if (t < 16) {
        float mx = -1e30f;
        float e[16];
        #pragma unroll
        for (int jj = 0; jj < 16; jj++) {
            float v = S[t][jj] * 0.0625f;
            e[jj] = v;
            mx = fmaxf(mx, v);
        }
        float sum = 0.f;
        #pragma unroll
        for (int jj = 0; jj < 16; jj++) { e[jj] = __expf(e[jj] - mx); sum += e[jj]; }
        float inv = 1.f / sum;
        #pragma unroll
        for (int jj = 0; jj < 16; jj++) Pm[t][jj] = e[jj] * inv;
    }
    __syncthreads();

    // out[i][p] = sum_j Pm[i][j] * v[j][p]; thread owns p = t + pc*256.
    // Register double-buffer on v rows.
    float acc[16][4];
    #pragma unroll
    for (int ii = 0; ii < 16; ii++)
        #pragma unroll
        for (int pc = 0; pc < 4; pc++) acc[ii][pc] = 0.f;

    float cv0, cv1, cv2, cv3, nv0, nv1, nv2, nv3;
    {
        const float* vp = &g_v[qbase];
        cv0 = vp[t + 0*256]; cv1 = vp[t + 1*256];
        cv2 = vp[t + 2*256]; cv3 = vp[t + 3*256];
    }
    #pragma unroll 1
    for (int jj = 0; jj < 16; jj++) {
        if (jj < 15) {
            const float* vp = &g_v[qbase + (size_t)(jj + 1) * CP];
            nv0 = vp[t + 0*256]; nv1 = vp[t + 1*256];
            nv2 = vp[t + 2*256]; nv3 = vp[t + 3*256];
        }
        #pragma unroll
        for (int ii = 0; ii < 16; ii++) {
            float pij = Pm[ii][jj];
            acc[ii][0] += pij * cv0;
            acc[ii][1] += pij * cv1;
            acc[ii][2] += pij * cv2;
            acc[ii][3] += pij * cv3;
        }
        cv0 = nv0; cv1 = nv1; cv2 = nv2; cv3 = nv3;
    }

    const float g = gamma[0];
    const size_t xbase = (size_t)b * CFP + (size_t)c * (FF * PP);
    #pragma unroll
    for (int ii = 0; ii < 16; ii++) {
        #pragma unroll
        for (int pc = 0; pc < 4; pc++) {
            size_t idx = xbase + (size_t)ii * PP + t + pc * 256;
            out[idx] = g * acc[ii][pc] + x[idx];
        }
    }
    #undef AT_ISSUE
}

// ---------------------------------------------------------------------------
extern "C" void kernel_launch(void* const* d_in, const int* in_sizes, int n_in,
                              void* d_out, int out_size)
{
    const float* x     = (const float*)d_in[0];
    const float* wq    = (const float*)d_in[1];
    const float* bq    = (const float*)d_in[2];
    const float* wk    = (const float*)d_in[3];
    const float* bk    = (const float*)d_in[4];
    const float* wv    = (const float*)d_in[5];
    const float* bv    = (const float*)d_in[6];
    const float* gamma = (const float*)d_in[7];
    float* out = (float*)d_out;

    cudaFuncSetAttribute(r15_proj,
                         cudaFuncAttributeMaxDynamicSharedMemorySize, PROJ_SMEM);
    cudaFuncSetAttribute(r15_attn,
                         cudaFuncAttributeMaxDynamicSharedMemorySize, ATTN_SMEM);

    r15_wsplit<<<384, 512>>>(wq, wk, wv);
    r15_xsplit<<<dim3(16, 4, 64), 256>>>(x);
    r15_proj<<<dim3(8, 6, 64), 256, PROJ_SMEM>>>(bq, bk, bv);
    r15_attn<<<BB*CC, 256, ATTN_SMEM>>>(x, gamma, out);
}

// round 16
// speedup vs baseline: 1.7468x; 1.6549x over previous
#include <cuda_runtime.h>
#include <cuda_fp16.h>
#include <cstdint>

// Problem constants
#define BB 4
#define CC 256
#define FF 16
#define PP 1024                 // H*W
#define NN 64                   // B*F
#define CP (CC*PP)              // 262144
#define CFP (CC*FF*PP)          // 4194304

// Scratch (allocation-guard-safe static device arrays). __align__(16): uint4/cp.async.
__device__ __align__(16) __half g_q[(size_t)NN*CP];
__device__ __align__(16) __half g_k[(size_t)NN*CP];
__device__ __align__(16) __half g_v[(size_t)NN*CP];
__device__ __align__(16) __half g_whi[3*CC*CC];
__device__ __align__(16) __half g_xthi[(size_t)NN*PP*CC];   // x fp16, transposed [n][p][c]

__device__ __forceinline__ uint32_t smem_u32(const void* p) {
    uint32_t a;
    asm("{ .reg .u64 t; cvta.to.shared.u64 t, %1; cvt.u32.u64 %0, t; }" : "=r"(a) : "l"(p));
    return a;
}

#define MMA16816(C, A, B)                                                     \
    asm volatile("mma.sync.aligned.m16n8k16.row.col.f32.f16.f16.f32 "         \
                 "{%0,%1,%2,%3}, {%4,%5,%6,%7}, {%8,%9}, {%0,%1,%2,%3};"      \
                 : "+f"((C)[0]), "+f"((C)[1]), "+f"((C)[2]), "+f"((C)[3])     \
                 : "r"((A)[0]), "r"((A)[1]), "r"((A)[2]), "r"((A)[3]),        \
                   "r"((B)[0]), "r"((B)[1]))

#define LDMX4(R, ADDR)                                                        \
    asm volatile("ldmatrix.sync.aligned.m8n8.x4.shared.b16 {%0,%1,%2,%3}, [%4];" \
                 : "=r"((R)[0]), "=r"((R)[1]), "=r"((R)[2]), "=r"((R)[3])     \
                 : "r"(ADDR))

#define LDMX2(R, ADDR)                                                        \
    asm volatile("ldmatrix.sync.aligned.m8n8.x2.shared.b16 {%0,%1}, [%2];"    \
                 : "=r"((R)[0]), "=r"((R)[1]) : "r"(ADDR))

#define CP16(SADDR, GPTR)                                                     \
    asm volatile("cp.async.ca.shared.global [%0], [%1], 16;"                  \
                 :: "r"(SADDR), "l"(GPTR))

// ---------------------------------------------------------------------------
// Kernel 0a: weights fp32 -> fp16
// ---------------------------------------------------------------------------
__global__ __launch_bounds__(512) void r16_wconv(
    const float* __restrict__ wq, const float* __restrict__ wk, const float* __restrict__ wv)
{
    int idx = blockIdx.x * 512 + threadIdx.x;
    const float* src = (idx < 65536) ? wq : (idx < 131072 ? wk : wv);
    g_whi[idx] = __float2half_rn(src[idx & 65535]);
}

// ---------------------------------------------------------------------------
// Kernel 0b: convert + transpose x: [n][c][p] fp32 -> [n][p][c] fp16.
// ---------------------------------------------------------------------------
__global__ __launch_bounds__(256) void r16_xconv(const float* __restrict__ x)
{
    __shared__ __align__(16) float tile[64][68];
    const int pt = blockIdx.x * 64;
    const int ct = blockIdx.y * 64;
    const int n  = blockIdx.z;
    const int t  = threadIdx.x;

    const float* __restrict__ xn = x + (size_t)n * CP;
    {
        int c   = t >> 2;
        int pc0 = (t & 3) * 16;
        const float* src = xn + (size_t)(ct + c) * PP + pt + pc0;
        #pragma unroll
        for (int u = 0; u < 4; u++)
            *(float4*)&tile[c][pc0 + u * 4] = *(const float4*)(src + u * 4);
    }
    __syncthreads();
    {
        int p   = t >> 2;
        int cc0 = (t & 3) * 16;
        __align__(16) __half hbuf[16];
        #pragma unroll
        for (int u = 0; u < 16; u++)
            hbuf[u] = __float2half_rn(tile[cc0 + u][p]);
        size_t dst = (size_t)n * PP * CC + (size_t)(pt + p) * CC + ct + cc0;
        *(uint4*)(g_xthi + dst)     = *(uint4*)hbuf;
        *(uint4*)(g_xthi + dst + 8) = *(uint4*)(hbuf + 8);
    }
}

// ---------------------------------------------------------------------------
// Kernel 1: QKV projection GEMM, single-term fp16 mma.sync (fp32 accum).
// Grid: (8, 6, 64): (p-tile, m*2+dh, n). CTA: C[128d x 128p], K=256 in 8
// chunks of 32, double-buffered, 2 CTAs/SM. Output fp16 with bias.
// ---------------------------------------------------------------------------
#define TILE_H 5120   // halves per tile (128*40)
#define PROJ_SMEM 40960

__global__ __launch_bounds__(256, 2) void r16_proj(
    const float* __restrict__ bq,
    const float* __restrict__ bk,
    const float* __restrict__ bv)
{
    extern __shared__ __align__(16) __half sh[];
    __half* As = sh;                 // [buf][TILE_H]
    __half* Bs = sh + 2 * TILE_H;    // [buf][TILE_H]

    const int p0 = blockIdx.x * 128;
    const int m  = blockIdx.y >> 1;
    const int d0 = (blockIdx.y & 1) * 128;
    const int n  = blockIdx.z;
    const int t  = threadIdx.x;
    const int lane = t & 31;
    const int wid  = t >> 5;
    const int wm   = wid & 1;
    const int wn   = wid >> 1;

    const __half* __restrict__ whp = g_whi + (size_t)m * 65536;

    float c[4][4][4];
    #pragma unroll
    for (int mi = 0; mi < 4; mi++)
        #pragma unroll
        for (int ni = 0; ni < 4; ni++)
            #pragma unroll
            for (int r = 0; r < 4; r++) c[mi][ni][r] = 0.f;

    const int arow = t >> 1;
    const int acol = (t & 1) * 16;
    const int brow = t >> 1;
    const int bseg = (t & 1) * 16;

    const __half* __restrict__ bhbase =
        g_xthi + (size_t)n * PP * CC + (size_t)(p0 + brow) * CC + bseg;

    uint4 rah0, rah1, rbh0, rbh1;

    #define TA_LDG(kc)                                                          \
        do {                                                                    \
            size_t wo = (size_t)(d0 + arow)*256 + (kc)*32 + acol;               \
            rah0 = *(const uint4*)(whp + wo);                                   \
            rah1 = *(const uint4*)(whp + wo + 8);                               \
            rbh0 = *(const uint4*)(bhbase + (kc)*32);                           \
            rbh1 = *(const uint4*)(bhbase + (kc)*32 + 8);                       \
        } while (0)

    #define TA_STS(buf)                                                         \
        do {                                                                    \
            __half* ah = As + (buf)*TILE_H;                                     \
            *(uint4*)&ah[arow*40 + acol]     = rah0;                            \
            *(uint4*)&ah[arow*40 + acol + 8] = rah1;                            \
            __half* bh = Bs + (buf)*TILE_H;                                     \
            *(uint4*)&bh[brow*40 + bseg]     = rbh0;                            \
            *(uint4*)&bh[brow*40 + bseg + 8] = rbh1;                            \
        } while (0)

    TA_LDG(0);
    TA_STS(0);
    __syncthreads();

    #pragma unroll 1
    for (int kc = 0; kc < 8; kc++) {
        if (kc < 7) TA_LDG(kc + 1);

        const uint32_t ah_s = smem_u32(As + (kc & 1)*TILE_H);
        const uint32_t bh_s = smem_u32(Bs + (kc & 1)*TILE_H);

        #pragma unroll
        for (int ks = 0; ks < 2; ks++) {
            const uint32_t a_off = (uint32_t)((wm*64 + (lane & 15))*40 + ks*16 + (lane >> 4)*8) * 2;
            const uint32_t b_off = (uint32_t)((wn*32 + (lane & 7))*40 + ks*16 + ((lane >> 3) & 1)*8) * 2;

            uint32_t af[4][4], bf[4][2];
            #pragma unroll
            for (int mi = 0; mi < 4; mi++)
                LDMX4(af[mi], ah_s + a_off + (uint32_t)(mi*16*40)*2);
            #pragma unroll
            for (int ni = 0; ni < 4; ni++)
                LDMX2(bf[ni], bh_s + b_off + (uint32_t)(ni*8*40)*2);
            #pragma unroll
            for (int mi = 0; mi < 4; mi++)
                #pragma unroll
                for (int ni = 0; ni < 4; ni++)
                    MMA16816(c[mi][ni], af[mi], bf[ni]);
        }

        if (kc < 7) TA_STS((kc + 1) & 1);
        __syncthreads();
    }

    // epilogue: bias + fp16 store
    const float* __restrict__ bias = (m == 0) ? bq : (m == 1) ? bk : bv;
    __half* __restrict__ ob = (m == 0) ? g_q : (m == 1) ? g_k : g_v;
    const int gid = lane >> 2, tid4 = lane & 3;
    const int col = p0 + wn*32 + tid4*2;

    #pragma unroll
    for (int mi = 0; mi < 4; mi++) {
        int d_r = d0 + wm*64 + mi*16 + gid;
        float b0 = bias[d_r];
        float b1 = bias[d_r + 8];
        __half* o0 = ob + (size_t)n*CP + (size_t)d_r*PP + col;
        __half* o1 = o0 + (size_t)8*PP;
        #pragma unroll
        for (int ni = 0; ni < 4; ni++) {
            *(__half2*)(o0 + ni*8) = __floats2half2_rn(c[mi][ni][0] + b0, c[mi][ni][1] + b0);
            *(__half2*)(o1 + ni*8) = __floats2half2_rn(c[mi][ni][2] + b1, c[mi][ni][3] + b1);
        }
    }
    #undef TA_LDG
    #undef TA_STS
}

// ---------------------------------------------------------------------------
// Kernel 2: per-(b,c) temporal attention on fp16 q/k/v, fp32 accumulation.
// cp.async 2-stage chunk pipeline; pad 280 halves -> conflict-free k reads.
// ---------------------------------------------------------------------------
#define QSC_H 280                     // halves per chunk row (256 + 24 pad)
#define QBUF_H (16*QSC_H)             // 4480 halves per buffer
#define ATTN_SMEM (4*QBUF_H*2)        // qs[2] + ks[2] = 35840 B

__global__ __launch_bounds__(256, 2) void r16_attn(
    const float* __restrict__ x,
    const float* __restrict__ gamma,
    float* __restrict__ out)
{
    extern __shared__ __align__(16) __half smh[];
    __shared__ float S[16][17];
    __shared__ float Pm[16][16];

    const int bc = blockIdx.x;
    const int b  = bc >> 8;
    const int c  = bc & 255;
    const int t  = threadIdx.x;

    const size_t qbase = (size_t)(b * 16) * CP + (size_t)c * PP;   // halves
    const uint32_t sbase = smem_u32(smh);

    // chunk of 256 p: per tensor 16 rows x 512B = 512 16B-segs; thread: 2 q + 2 k
    #define AT_ISSUE(ch, bf) do {                                               \
        _Pragma("unroll")                                                       \
        for (int u = 0; u < 2; u++) {                                           \
            int s = t + u * 256;                                                \
            int row = s >> 5, o16 = s & 31;                                     \
            uint32_t so = sbase + ((uint32_t)(bf)*QBUF_H + row*QSC_H + o16*8)*2;\
            size_t go = qbase + (size_t)row*CP + (ch)*256 + o16*8;              \
            CP16(so, g_q + go);                                                 \
            CP16(so + 2*QBUF_H*2, g_k + go);                                    \
        }                                                                       \
        asm volatile("cp.async.commit_group;" ::: "memory");                    \
    } while (0)

    AT_ISSUE(0, 0);
    AT_ISSUE(1, 1);

    const int i = t >> 4, j = t & 15;
    float s0 = 0.f, s1 = 0.f, s2 = 0.f, s3 = 0.f;

    #pragma unroll 1
    for (int ch = 0; ch < 4; ch++) {
        if (ch < 3) asm volatile("cp.async.wait_group 1;" ::: "memory");
        else        asm volatile("cp.async.wait_group 0;" ::: "memory");
        __syncthreads();

        const __half* qp = smh + (ch & 1)*QBUF_H + i*QSC_H;
        const __half* kp = smh + (2 + (ch & 1))*QBUF_H + j*QSC_H;
        #pragma unroll 4
        for (int p = 0; p < 256; p += 8) {
            uint4 qa = *(const uint4*)(qp + p);
            uint4 ka = *(const uint4*)(kp + p);
            const __half2* qh = (const __half2*)&qa;
            const __half2* kh = (const __half2*)&ka;
            #pragma unroll
            for (int u = 0; u < 4; u++) {
                float2 qf = __half22float2(qh[u]);
                float2 kf = __half22float2(kh[u]);
                s0 += qf.x * kf.x;
                s1 += qf.y * kf.y;
            }
        }
        __syncthreads();
        if (ch < 2) AT_ISSUE(ch + 2, ch & 1);
    }
    S[i][j] = (s0 + s1) + (s2 + s3);
    __syncthreads();

    // softmax rows (scale 1/sqrt(256))
    if (t < 16) {
        float mx = -1e30f;
        float e[16];
        #pragma unroll
        for (int jj = 0; jj < 16; jj++) {
            float v = S[t][jj] * 0.0625f;
            e[jj] = v;
            mx = fmaxf(mx, v);
        }
        float sum = 0.f;
        #pragma unroll
        for (int jj = 0; jj < 16; jj++) { e[jj] = __expf(e[jj] - mx); sum += e[jj]; }
        float inv = 1.f / sum;
        #pragma unroll
        for (int jj = 0; jj < 16; jj++) Pm[t][jj] = e[jj] * inv;
    }
    __syncthreads();

    // out[ii][p] = sum_j Pm[ii][j] * v[j][p]; thread owns half2 idx t and t+256
    float acc[16][4];
    #pragma unroll
    for (int ii = 0; ii < 16; ii++)
        #pragma unroll
        for (int pc = 0; pc < 4; pc++) acc[ii][pc] = 0.f;

    __half2 cva, cvb, nva, nvb;
    {
        const __half2* vp2 = (const __half2*)(g_v + qbase);
        cva = vp2[t]; cvb = vp2[t + 256];
    }
    #pragma unroll 1
    for (int jj = 0; jj < 16; jj++) {
        if (jj < 15) {
            const __half2* vp2 = (const __half2*)(g_v + qbase + (size_t)(jj + 1) * CP);
            nva = vp2[t]; nvb = vp2[t + 256];
        }
        float2 fa = __half22float2(cva);
        float2 fb = __half22float2(cvb);
        #pragma unroll
        for (int ii = 0; ii < 16; ii++) {
            float pij = Pm[ii][jj];
            acc[ii][0] += pij * fa.x;
            acc[ii][1] += pij * fa.y;
            acc[ii][2] += pij * fb.x;
            acc[ii][3] += pij * fb.y;
        }
        cva = nva; cvb = nvb;
    }

    const float g = gamma[0];
    const size_t xbase = (size_t)b * CFP + (size_t)c * (FF * PP);
    #pragma unroll
    for (int ii = 0; ii < 16; ii++) {
        size_t idx = xbase + (size_t)ii * PP + 2*t;
        float2 xv0 = *(const float2*)&x[idx];
        float2 xv1 = *(const float2*)&x[idx + 512];
        *(float2*)&out[idx]       = make_float2(g*acc[ii][0] + xv0.x, g*acc[ii][1] + xv0.y);
        *(float2*)&out[idx + 512] = make_float2(g*acc[ii][2] + xv1.x, g*acc[ii][3] + xv1.y);
    }
    #undef AT_ISSUE
}

// ---------------------------------------------------------------------------
extern "C" void kernel_launch(void* const* d_in, const int* in_sizes, int n_in,
                              void* d_out, int out_size)
{
    const float* x     = (const float*)d_in[0];
    const float* wq    = (const float*)d_in[1];
    const float* bq    = (const float*)d_in[2];
    const float* wk    = (const float*)d_in[3];
    const float* bk    = (const float*)d_in[4];
    const float* wv    = (const float*)d_in[5];
    const float* bv    = (const float*)d_in[6];
    const float* gamma = (const float*)d_in[7];
    float* out = (float*)d_out;

    cudaFuncSetAttribute(r16_proj,
                         cudaFuncAttributeMaxDynamicSharedMemorySize, PROJ_SMEM);
    cudaFuncSetAttribute(r16_attn,
                         cudaFuncAttributeMaxDynamicSharedMemorySize, ATTN_SMEM);

    r16_wconv<<<384, 512>>>(wq, wk, wv);
    r16_xconv<<<dim3(16, 4, 64), 256>>>(x);
    r16_proj<<<dim3(8, 6, 64), 256, PROJ_SMEM>>>(bq, bk, bv);
    r16_attn<<<BB*CC, 256, ATTN_SMEM>>>(x, gamma, out);
}

// round 17
// speedup vs baseline: 2.0867x; 1.1946x over previous
#include <cuda_runtime.h>
#include <cuda_fp16.h>
#include <cstdint>

// Problem constants
#define BB 4
#define CC 256
#define FF 16
#define PP 1024                 // H*W
#define NN 64                   // B*F
#define CP (CC*PP)              // 262144
#define CFP (CC*FF*PP)          // 4194304

// Scratch (allocation-guard-safe static device arrays). __align__(16): uint4/cp.async.
__device__ __align__(16) __half g_q[(size_t)NN*CP];
__device__ __align__(16) __half g_k[(size_t)NN*CP];
__device__ __align__(16) __half g_v[(size_t)NN*CP];
__device__ __align__(16) __half g_whi[3*CC*CC];
__device__ __align__(16) __half g_xthi[(size_t)NN*PP*CC];   // x fp16, transposed [n][p][c]

__device__ __forceinline__ uint32_t smem_u32(const void* p) {
    uint32_t a;
    asm("{ .reg .u64 t; cvta.to.shared.u64 t, %1; cvt.u32.u64 %0, t; }" : "=r"(a) : "l"(p));
    return a;
}

#define MMA16816(C, A, B)                                                     \
    asm volatile("mma.sync.aligned.m16n8k16.row.col.f32.f16.f16.f32 "         \
                 "{%0,%1,%2,%3}, {%4,%5,%6,%7}, {%8,%9}, {%0,%1,%2,%3};"      \
                 : "+f"((C)[0]), "+f"((C)[1]), "+f"((C)[2]), "+f"((C)[3])     \
                 : "r"((A)[0]), "r"((A)[1]), "r"((A)[2]), "r"((A)[3]),        \
                   "r"((B)[0]), "r"((B)[1]))

#define LDMX4(R, ADDR)                                                        \
    asm volatile("ldmatrix.sync.aligned.m8n8.x4.shared.b16 {%0,%1,%2,%3}, [%4];" \
                 : "=r"((R)[0]), "=r"((R)[1]), "=r"((R)[2]), "=r"((R)[3])     \
                 : "r"(ADDR))

#define LDMX2(R, ADDR)                                                        \
    asm volatile("ldmatrix.sync.aligned.m8n8.x2.shared.b16 {%0,%1}, [%2];"    \
                 : "=r"((R)[0]), "=r"((R)[1]) : "r"(ADDR))

#define CP16(SADDR, GPTR)                                                     \
    asm volatile("cp.async.ca.shared.global [%0], [%1], 16;"                  \
                 :: "r"(SADDR), "l"(GPTR))

// ---------------------------------------------------------------------------
// Kernel 0a: weights fp32 -> fp16
// ---------------------------------------------------------------------------
__global__ __launch_bounds__(512) void r17_wconv(
    const float* __restrict__ wq, const float* __restrict__ wk, const float* __restrict__ wv)
{
    int idx = blockIdx.x * 512 + threadIdx.x;
    const float* src = (idx < 65536) ? wq : (idx < 131072 ? wk : wv);
    g_whi[idx] = __float2half_rn(src[idx & 65535]);
}

// ---------------------------------------------------------------------------
// Kernel 0b: convert + transpose x: [n][c][p] fp32 -> [n][p][c] fp16.
// ---------------------------------------------------------------------------
__global__ __launch_bounds__(256) void r17_xconv(const float* __restrict__ x)
{
    __shared__ __align__(16) float tile[64][68];
    const int pt = blockIdx.x * 64;
    const int ct = blockIdx.y * 64;
    const int n  = blockIdx.z;
    const int t  = threadIdx.x;

    const float* __restrict__ xn = x + (size_t)n * CP;
    {
        int c   = t >> 2;
        int pc0 = (t & 3) * 16;
        const float* src = xn + (size_t)(ct + c) * PP + pt + pc0;
        #pragma unroll
        for (int u = 0; u < 4; u++)
            *(float4*)&tile[c][pc0 + u * 4] = *(const float4*)(src + u * 4);
    }
    __syncthreads();
    {
        int p   = t >> 2;
        int cc0 = (t & 3) * 16;
        __align__(16) __half hbuf[16];
        #pragma unroll
        for (int u = 0; u < 16; u++)
            hbuf[u] = __float2half_rn(tile[cc0 + u][p]);
        size_t dst = (size_t)n * PP * CC + (size_t)(pt + p) * CC + ct + cc0;
        *(uint4*)(g_xthi + dst)     = *(uint4*)hbuf;
        *(uint4*)(g_xthi + dst + 8) = *(uint4*)(hbuf + 8);
    }
}

// ---------------------------------------------------------------------------
// Kernel 1: QKV projection GEMM, single-term fp16 mma.sync, cp.async 3-stage.
// Grid: (8, 6, 64): (p-tile, m*2+dh, n). CTA: C[128d x 128p], K=256 in 8
// chunks of 32. smem: 3 stages x (A 10240B + B 10240B) = 61440 B, 2 CTAs/SM.
// ---------------------------------------------------------------------------
#define TILE_H 5120               // halves per A (or B) tile (128*40)
#define STAGE_B 20480             // bytes per stage
#define PROJ_SMEM (3*STAGE_B)     // 61440

__global__ __launch_bounds__(256, 2) void r17_proj(
    const float* __restrict__ bq,
    const float* __restrict__ bk,
    const float* __restrict__ bv)
{
    extern __shared__ __align__(16) __half sh[];

    const int p0 = blockIdx.x * 128;
    const int m  = blockIdx.y >> 1;
    const int d0 = (blockIdx.y & 1) * 128;
    const int n  = blockIdx.z;
    const int t  = threadIdx.x;
    const int lane = t & 31;
    const int wid  = t >> 5;
    const int wm   = wid & 1;
    const int wn   = wid >> 1;

    const __half* __restrict__ whp = g_whi + (size_t)m * 65536;
    const __half* __restrict__ bh0 = g_xthi + (size_t)n * PP * CC + (size_t)p0 * CC;
    const uint32_t sbase = smem_u32(sh);

    float c[4][4][4];
    #pragma unroll
    for (int mi = 0; mi < 4; mi++)
        #pragma unroll
        for (int ni = 0; ni < 4; ni++)
            #pragma unroll
            for (int r = 0; r < 4; r++) c[mi][ni][r] = 0.f;

    // per chunk: A 512 16B-segs, B 512 16B-segs; thread does 2 of each.
    #define P_ISSUE(kc, stg) do {                                               \
        uint32_t base = sbase + (uint32_t)(stg)*STAGE_B;                        \
        _Pragma("unroll")                                                       \
        for (int u = 0; u < 2; u++) {                                           \
            int sid = t + u*256;                                                \
            int row = sid >> 2, sg = sid & 3;                                   \
            uint32_t so = base + (uint32_t)(row*40 + sg*8)*2;                   \
            CP16(so, whp + (size_t)(d0 + row)*256 + (kc)*32 + sg*8);            \
            CP16(so + TILE_H*2, bh0 + (size_t)row*CC + (kc)*32 + sg*8);         \
        }                                                                       \
        asm volatile("cp.async.commit_group;" ::: "memory");                    \
    } while (0)

    P_ISSUE(0, 0);
    P_ISSUE(1, 1);
    P_ISSUE(2, 2);

    #pragma unroll 1
    for (int kc = 0; kc < 8; kc++) {
        if (kc < 6)      asm volatile("cp.async.wait_group 2;" ::: "memory");
        else if (kc == 6) asm volatile("cp.async.wait_group 1;" ::: "memory");
        else             asm volatile("cp.async.wait_group 0;" ::: "memory");
        __syncthreads();

        const uint32_t ah_s = sbase + (uint32_t)(kc % 3)*STAGE_B;
        const uint32_t bh_s = ah_s + TILE_H*2;

        #pragma unroll
        for (int ks = 0; ks < 2; ks++) {
            const uint32_t a_off = (uint32_t)((wm*64 + (lane & 15))*40 + ks*16 + (lane >> 4)*8) * 2;
            const uint32_t b_off = (uint32_t)((wn*32 + (lane & 7))*40 + ks*16 + ((lane >> 3) & 1)*8) * 2;

            uint32_t af[4][4], bf[4][2];
            #pragma unroll
            for (int mi = 0; mi < 4; mi++)
                LDMX4(af[mi], ah_s + a_off + (uint32_t)(mi*16*40)*2);
            #pragma unroll
            for (int ni = 0; ni < 4; ni++)
                LDMX2(bf[ni], bh_s + b_off + (uint32_t)(ni*8*40)*2);
            #pragma unroll
            for (int mi = 0; mi < 4; mi++)
                #pragma unroll
                for (int ni = 0; ni < 4; ni++)
                    MMA16816(c[mi][ni], af[mi], bf[ni]);
        }
        __syncthreads();
        if (kc < 5) P_ISSUE(kc + 3, (kc + 3) % 3);
    }

    // epilogue: bias + fp16 store
    const float* __restrict__ bias = (m == 0) ? bq : (m == 1) ? bk : bv;
    __half* __restrict__ ob = (m == 0) ? g_q : (m == 1) ? g_k : g_v;
    const int gid = lane >> 2, tid4 = lane & 3;
    const int col = p0 + wn*32 + tid4*2;

    #pragma unroll
    for (int mi = 0; mi < 4; mi++) {
        int d_r = d0 + wm*64 + mi*16 + gid;
        float b0 = bias[d_r];
        float b1 = bias[d_r + 8];
        __half* o0 = ob + (size_t)n*CP + (size_t)d_r*PP + col;
        __half* o1 = o0 + (size_t)8*PP;
        #pragma unroll
        for (int ni = 0; ni < 4; ni++) {
            *(__half2*)(o0 + ni*8) = __floats2half2_rn(c[mi][ni][0] + b0, c[mi][ni][1] + b0);
            *(__half2*)(o1 + ni*8) = __floats2half2_rn(c[mi][ni][2] + b1, c[mi][ni][3] + b1);
        }
    }
    #undef P_ISSUE
}

// ---------------------------------------------------------------------------
// Kernel 2: per-(b,c) temporal attention on fp16 q/k/v.
// q/k: cp.async 2-stage chunk pipeline. v: prefetched into smem at kernel
// start (overlaps with entire logits phase). 2 CTAs/SM.
// ---------------------------------------------------------------------------
#define QSC_H 280                     // halves per q/k chunk row (256 + 24 pad)
#define QBUF_H (16*QSC_H)             // 4480 halves per buffer
#define VS_H 1032                     // halves per v row (1024 + 8 pad)
#define VOFF_H (4*QBUF_H)             // v buffer offset (halves)
#define ATTN_SMEM ((4*QBUF_H + 16*VS_H)*2)   // 35840 + 33024 = 68864 B

__global__ __launch_bounds__(256, 2) void r17_attn(
    const float* __restrict__ x,
    const float* __restrict__ gamma,
    float* __restrict__ out)
{
    extern __shared__ __align__(16) __half smh[];
    __shared__ float S[16][17];
    __shared__ float Pm[16][16];

    const int bc = blockIdx.x;
    const int b  = bc >> 8;
    const int c  = bc & 255;
    const int t  = threadIdx.x;

    const size_t qbase = (size_t)(b * 16) * CP + (size_t)c * PP;   // halves
    const uint32_t sbase = smem_u32(smh);

    // q/k chunk of 256 p: per tensor 512 16B-segs; thread: 2 q + 2 k
    #define AT_ISSUE(ch, bf) do {                                               \
        _Pragma("unroll")                                                       \
        for (int u = 0; u < 2; u++) {                                           \
            int s = t + u * 256;                                                \
            int row = s >> 5, o16 = s & 31;                                     \
            uint32_t so = sbase + ((uint32_t)(bf)*QBUF_H + row*QSC_H + o16*8)*2;\
            size_t go = qbase + (size_t)row*CP + (ch)*256 + o16*8;              \
            CP16(so, g_q + go);                                                 \
            CP16(so + 2*QBUF_H*2, g_k + go);                                    \
        }                                                                       \
        asm volatile("cp.async.commit_group;" ::: "memory");                    \
    } while (0)

    // group order: g0=qk0, g1=qk1, g2=v(all 32KB), then g3=qk2, g4=qk3
    AT_ISSUE(0, 0);
    AT_ISSUE(1, 1);
    {   // v: 16 rows x 2KB = 2048 segs; thread does 8
        #pragma unroll
        for (int u = 0; u < 8; u++) {
            int s = t + u * 256;
            int row = s >> 7, o16 = s & 127;
            uint32_t so = sbase + ((uint32_t)VOFF_H + row*VS_H + o16*8)*2;
            CP16(so, g_v + qbase + (size_t)row*CP + o16*8);
        }
        asm volatile("cp.async.commit_group;" ::: "memory");
    }

    const int i = t >> 4, j = t & 15;
    float s0 = 0.f, s1 = 0.f, s2 = 0.f, s3 = 0.f;

    #pragma unroll 1
    for (int ch = 0; ch < 4; ch++) {
        // groups needed in order; see ordering comment above
        if (ch < 2)      asm volatile("cp.async.wait_group 2;" ::: "memory");
        else if (ch == 2) asm volatile("cp.async.wait_group 1;" ::: "memory");
        else             asm volatile("cp.async.wait_group 0;" ::: "memory");
        __syncthreads();

        const __half* qp = smh + (ch & 1)*QBUF_H + i*QSC_H;
        const __half* kp = smh + (2 + (ch & 1))*QBUF_H + j*QSC_H;
        #pragma unroll 4
        for (int p = 0; p < 256; p += 8) {
            uint4 qa = *(const uint4*)(qp + p);
            uint4 ka = *(const uint4*)(kp + p);
            const __half2* qh = (const __half2*)&qa;
            const __half2* kh = (const __half2*)&ka;
            #pragma unroll
            for (int u = 0; u < 4; u++) {
                float2 qf = __half22float2(qh[u]);
                float2 kf = __half22float2(kh[u]);
                s0 += qf.x * kf.x;
                s1 += qf.y * kf.y;
            }
        }
        __syncthreads();
        if (ch < 2) AT_ISSUE(ch + 2, ch & 1);
    }
    S[i][j] = (s0 + s1) + (s2 + s3);
    __syncthreads();

    // softmax rows (scale 1/sqrt(256))
    if (t < 16) {
        float mx = -1e30f;
        float e[16];
        #pragma unroll
        for (int jj = 0; jj < 16; jj++) {
            float v = S[t][jj] * 0.0625f;
            e[jj] = v;
            mx = fmaxf(mx, v);
        }
        float sum = 0.f;
        #pragma unroll
        for (int jj = 0; jj < 16; jj++) { e[jj] = __expf(e[jj] - mx); sum += e[jj]; }
        float inv = 1.f / sum;
        #pragma unroll
        for (int jj = 0; jj < 16; jj++) Pm[t][jj] = e[jj] * inv;
    }
    __syncthreads();

    // out[ii][p] = sum_j Pm[ii][j] * v[j][p]; v now in smem. Thread owns
    // half2 index t and t+256.
    float acc[16][4];
    #pragma unroll
    for (int ii = 0; ii < 16; ii++)
        #pragma unroll
        for (int pc = 0; pc < 4; pc++) acc[ii][pc] = 0.f;

    #pragma unroll 1
    for (int jj = 0; jj < 16; jj++) {
        const __half2* vp2 = (const __half2*)(smh + VOFF_H + jj*VS_H);
        float2 fa = __half22float2(vp2[t]);
        float2 fb = __half22float2(vp2[t + 256]);
        #pragma unroll
        for (int ii = 0; ii < 16; ii++) {
            float pij = Pm[ii][jj];
            acc[ii][0] += pij * fa.x;
            acc[ii][1] += pij * fa.y;
            acc[ii][2] += pij * fb.x;
            acc[ii][3] += pij * fb.y;
        }
    }

    const float g = gamma[0];
    const size_t xbase = (size_t)b * CFP + (size_t)c * (FF * PP);
    #pragma unroll
    for (int ii = 0; ii < 16; ii++) {
        size_t idx = xbase + (size_t)ii * PP + 2*t;
        float2 xv0 = *(const float2*)&x[idx];
        float2 xv1 = *(const float2*)&x[idx + 512];
        *(float2*)&out[idx]       = make_float2(g*acc[ii][0] + xv0.x, g*acc[ii][1] + xv0.y);
        *(float2*)&out[idx + 512] = make_float2(g*acc[ii][2] + xv1.x, g*acc[ii][3] + xv1.y);
    }
    #undef AT_ISSUE
}

// ---------------------------------------------------------------------------
extern "C" void kernel_launch(void* const* d_in, const int* in_sizes, int n_in,
                              void* d_out, int out_size)
{
    const float* x     = (const float*)d_in[0];
    const float* wq    = (const float*)d_in[1];
    const float* bq    = (const float*)d_in[2];
    const float* wk    = (const float*)d_in[3];
    const float* bk    = (const float*)d_in[4];
    const float* wv    = (const float*)d_in[5];
    const float* bv    = (const float*)d_in[6];
    const float* gamma = (const float*)d_in[7];
    float* out = (float*)d_out;

    cudaFuncSetAttribute(r17_proj,
                         cudaFuncAttributeMaxDynamicSharedMemorySize, PROJ_SMEM);
    cudaFuncSetAttribute(r17_attn,
                         cudaFuncAttributeMaxDynamicSharedMemorySize, ATTN_SMEM);

    r17_wconv<<<384, 512>>>(wq, wk, wv);
    r17_xconv<<<dim3(16, 4, 64), 256>>>(x);
    r17_proj<<<dim3(8, 6, 64), 256, PROJ_SMEM>>>(bq, bk, bv);
    r17_attn<<<BB*CC, 256, ATTN_SMEM>>>(x, gamma, out);
}